// round 9
// baseline (speedup 1.0000x reference)
#include <cuda_runtime.h>
#include <cuda_bf16.h>
#include <cstdint>

// Spatially-varying 19x19 blur.
// out[b,c,i,j] = (1/361) * sum_{u,v} x_reflectpad[b,c,i+u-9,j+v-9] * kernel[b,u*19+v,i,j]
//
// B=2, C=3, H=W=256, L=19, K2=361. Kernel tensor (189 MB) read exactly once.
// R9 = R6 (best) + L2 prefetch pipeline:
//  - prefetch.global.L2 of row u+2's 19 taps (2KB each), spread over the group
//  - prologue prefetch of first 2 rows overlaps the patch-staging phase
//  - __ldcg for kv loads (L2-only, no L1 pollution; data is zero-reuse)

#define LK    19
#define PADR  9
#define HGT   256
#define WID   256
#define HW    (HGT * WID)
#define K2    (LK * LK)

#define TJ    256     // full row
#define TI    2
#define PGRP  128     // pixel-group threads: 64 j-threads x 2 rows, 4 px each
#define NGRP  4       // tap groups
#define NTHR  (PGRP * NGRP)      // 512
#define PCOLS (TJ + LK - 1)      // 274
#define PROWS (TI + LK - 1)      // 20
#define PITCH 276                // 16B-aligned float4 rows

#define PFU   2                  // prefetch distance in u-rows
#define TAPB  (TI * WID * 4)     // 2048 bytes per tap
#define LINES_PER_ROW (LK * (TAPB / 128))   // 19*16 = 304

#define PATCH_FLOATS (3 * PROWS * PITCH)        // 16560
#define PART_FLOATS  ((NGRP - 1) * PGRP * 13)   // 4992
#define SMEM_BYTES   ((PATCH_FLOATS + PART_FLOATS) * 4)   // 86208

__device__ __forceinline__ void pf_l2(const void* p) {
    asm volatile("prefetch.global.L2 [%0];" :: "l"(p));
}

// prefetch all 19 taps of u-row 'u' (block-level 2KB spans), spread over group
__device__ __forceinline__ void prefetch_row(const char* pfb, int u, int tid2) {
    const size_t row_off = (size_t)u * LK * HW * 4;
    #pragma unroll
    for (int e = tid2; e < LINES_PER_ROW; e += PGRP) {
        const int v = e >> 4;          // tap within row
        const int l = e & 15;          // 128B line within 2KB tap span
        pf_l2(pfb + row_off + (size_t)v * HW * 4 + l * 128);
    }
}

__global__ __launch_bounds__(NTHR, 2)
void svblur_kernel(const float* __restrict__ x,
                   const float* __restrict__ kern,
                   float* __restrict__ out)
{
    extern __shared__ float dsm[];
    float* patch = dsm;                    // [3][PROWS][PITCH]
    float* part  = dsm + PATCH_FLOATS;     // [NGRP-1][PGRP][13]

    const int tid = threadIdx.x;
    const int ip  = blockIdx.x;   // 0..127 : i-pair
    const int b   = blockIdx.y;   // 0..1
    const int i0  = ip * TI;

    const int g    = tid >> 7;             // tap group 0..3
    const int tid2 = tid & (PGRP - 1);     // 0..127
    const int u_lo = (g * LK) / NGRP;          // 0,4,9,14
    const int u_hi = ((g + 1) * LK) / NGRP;    // 4,9,14,19

    // block-level prefetch base: kern[b][.][i0..i0+1][:]
    const char* pfb = (const char*)(kern + (size_t)b * K2 * HW + (size_t)i0 * WID);

    // ---- prologue prefetch: first PFU rows of this group's range ----
    prefetch_row(pfb, u_lo, tid2);
    if (u_lo + 1 < u_hi) prefetch_row(pfb, u_lo + 1, tid2);

    // ---- stage input patch (reflect padding), all 3 channels ----
    const float* xb = x + (size_t)b * 3 * HW;
    for (int e = tid; e < PROWS * PCOLS; e += NTHR) {
        int pr = e / PCOLS;
        int pc = e - pr * PCOLS;
        int gi = i0 - PADR + pr;
        int gj = -PADR + pc;
        gi = (gi < 0) ? -gi : ((gi >= HGT) ? 2 * (HGT - 1) - gi : gi);
        gj = (gj < 0) ? -gj : ((gj >= WID) ? 2 * (WID - 1) - gj : gj);
        const float* src = xb + gi * WID + gj;
        patch[(0 * PROWS + pr) * PITCH + pc] = src[0 * HW];
        patch[(1 * PROWS + pr) * PITCH + pc] = src[1 * HW];
        patch[(2 * PROWS + pr) * PITCH + pc] = src[2 * HW];
    }
    __syncthreads();

    const int jthr = tid2 & 63;            // 0..63
    const int ir   = tid2 >> 6;            // 0..1
    const int i    = i0 + ir;
    const int jj   = jthr * 4;             // local j of first of 4 px

    const float4* kp = (const float4*)(kern + (size_t)b * K2 * HW
                                            + (size_t)i * WID + jj);

    float a0[4] = {0.f, 0.f, 0.f, 0.f};
    float a1[4] = {0.f, 0.f, 0.f, 0.f};
    float a2[4] = {0.f, 0.f, 0.f, 0.f};

    #pragma unroll 1
    for (int u = u_lo; u < u_hi; u++) {
        // software prefetch pipeline: row u+PFU -> L2
        if (u + PFU < u_hi) prefetch_row(pfb, u + PFU, tid2);

        const float4* kru = kp + (size_t)u * LK * (HW / 4);
        const float4* r0  = (const float4*)&patch[(0 * PROWS + ir + u) * PITCH];
        const float4* r1  = (const float4*)&patch[(1 * PROWS + ir + u) * PITCH];
        const float4* r2  = (const float4*)&patch[(2 * PROWS + ir + u) * PITCH];
        const int jb = jthr;

        #pragma unroll
        for (int vb = 0; vb < 5; vb++) {          // v chunks: 4,4,4,4,3
            const int vmax = (vb == 4) ? 3 : 4;
            float4 kv[4];
            #pragma unroll
            for (int s = 0; s < 4; s++) {
                if (s >= vmax) break;
                kv[s] = __ldcg(kru + (size_t)(vb * 4 + s) * (HW / 4));
            }
            float4 lo0 = r0[jb + vb], hi0 = r0[jb + vb + 1];
            float4 lo1 = r1[jb + vb], hi1 = r1[jb + vb + 1];
            float4 lo2 = r2[jb + vb], hi2 = r2[jb + vb + 1];
            float w0[8] = {lo0.x, lo0.y, lo0.z, lo0.w, hi0.x, hi0.y, hi0.z, hi0.w};
            float w1[8] = {lo1.x, lo1.y, lo1.z, lo1.w, hi1.x, hi1.y, hi1.z, hi1.w};
            float w2[8] = {lo2.x, lo2.y, lo2.z, lo2.w, hi2.x, hi2.y, hi2.z, hi2.w};

            #pragma unroll
            for (int s = 0; s < 4; s++) {
                if (s >= vmax) break;
                a0[0] += w0[s + 0] * kv[s].x;  a0[1] += w0[s + 1] * kv[s].y;
                a0[2] += w0[s + 2] * kv[s].z;  a0[3] += w0[s + 3] * kv[s].w;
                a1[0] += w1[s + 0] * kv[s].x;  a1[1] += w1[s + 1] * kv[s].y;
                a1[2] += w1[s + 2] * kv[s].z;  a1[3] += w1[s + 3] * kv[s].w;
                a2[0] += w2[s + 0] * kv[s].x;  a2[1] += w2[s + 1] * kv[s].y;
                a2[2] += w2[s + 2] * kv[s].z;  a2[3] += w2[s + 3] * kv[s].w;
            }
        }
    }

    // ---- combine the 4 tap-groups ----
    if (g > 0) {
        float* p = part + ((g - 1) * PGRP + tid2) * 13;
        #pragma unroll
        for (int t = 0; t < 4; t++) { p[t] = a0[t]; p[4 + t] = a1[t]; p[8 + t] = a2[t]; }
    }
    __syncthreads();
    if (g == 0) {
        #pragma unroll
        for (int q = 0; q < NGRP - 1; q++) {
            const float* p = part + (q * PGRP + tid2) * 13;
            #pragma unroll
            for (int t = 0; t < 4; t++) {
                a0[t] += p[t]; a1[t] += p[4 + t]; a2[t] += p[8 + t];
            }
        }
        const float inv = 1.0f / (float)K2;
        float* ob = out + (size_t)b * 3 * HW + (size_t)i * WID + jj;
        float4 o0 = make_float4(a0[0]*inv, a0[1]*inv, a0[2]*inv, a0[3]*inv);
        float4 o1 = make_float4(a1[0]*inv, a1[1]*inv, a1[2]*inv, a1[3]*inv);
        float4 o2 = make_float4(a2[0]*inv, a2[1]*inv, a2[2]*inv, a2[3]*inv);
        *(float4*)(ob + 0 * HW) = o0;
        *(float4*)(ob + 1 * HW) = o1;
        *(float4*)(ob + 2 * HW) = o2;
    }
}

extern "C" void kernel_launch(void* const* d_in, const int* in_sizes, int n_in,
                              void* d_out, int out_size)
{
    const float* x    = (const float*)d_in[0];
    const float* kern = (const float*)d_in[1];
    // defensive: identify tensors by size (input = 393216, kernel = 47316992)
    if (n_in >= 2 && in_sizes[0] > in_sizes[1]) {
        const float* t = x; x = kern; kern = t;
    }

    cudaFuncSetAttribute(svblur_kernel,
                         cudaFuncAttributeMaxDynamicSharedMemorySize, SMEM_BYTES);

    dim3 grid(HGT / TI, 2);   // (128, 2) = 256 blocks, 16 warps each
    svblur_kernel<<<grid, NTHR, SMEM_BYTES>>>(x, kern, (float*)d_out);
}

// round 10
// speedup vs baseline: 1.2461x; 1.2461x over previous
#include <cuda_runtime.h>
#include <cuda_bf16.h>
#include <cstdint>

// Spatially-varying 19x19 blur.
// out[b,c,i,j] = (1/361) * sum_{u,v} x_reflectpad[b,c,i+u-9,j+v-9] * kernel[b,u*19+v,i,j]
//
// R10: warp-private cp.async.cg double-buffered pipeline for the kernel tensor.
// Each warp streams chunks c = wid + 8*s (4 taps x 2 rows x 512B = 4KB/chunk)
// into its own 2-stage smem ring; commit/wait_group only (no mbarrier, no
// in-loop __syncthreads -> no deadlock class). Each lane copies exactly the
// 16B it consumes. Partials reduced across warps via reused ring smem.
// Traffic = exactly 189MB (each line fetched once by its consumer).

#define LK    19
#define PADR  9
#define HGT   256
#define WID   256
#define HW    (HGT * WID)
#define K2    (LK * LK)

#define TJ    128
#define TI    2
#define NTHR  256
#define NW    8
#define PCOLS (TJ + LK - 1)      // 146
#define PROWS (TI + LK - 1)      // 20
#define PITCH 148                // float4-aligned rows

#define NCHUNK 95                // (u, vb) pairs: 19 * 5
#define STAGE_FLOATS 1024        // 4 taps x 2 rows x 128 floats = 4KB
#define PATCH_FLOATS (3 * PROWS * PITCH)              // 8880
#define RING_FLOATS  (NW * 2 * STAGE_FLOATS)          // 16384
#define SMEM_BYTES   ((PATCH_FLOATS + RING_FLOATS) * 4)   // 101056

__device__ __forceinline__ uint32_t smem_u32(const void* p) {
    return (uint32_t)__cvta_generic_to_shared(p);
}
__device__ __forceinline__ void cp16(uint32_t dst, const void* src) {
    asm volatile("cp.async.cg.shared.global [%0], [%1], 16;" :: "r"(dst), "l"(src));
}
__device__ __forceinline__ void cp_commit() {
    asm volatile("cp.async.commit_group;" ::: "memory");
}
template <int N> __device__ __forceinline__ void cp_wait() {
    asm volatile("cp.async.wait_group %0;" :: "n"(N) : "memory");
}

__global__ __launch_bounds__(NTHR, 2)
void svblur_kernel(const float* __restrict__ x,
                   const float* __restrict__ kern,
                   float* __restrict__ out)
{
    extern __shared__ float dsm[];
    float* patch = dsm;                     // [3][PROWS][PITCH]
    float* ring  = dsm + PATCH_FLOATS;      // [NW][2][STAGE_FLOATS]

    const int tid  = threadIdx.x;
    const int wid  = tid >> 5;
    const int lane = tid & 31;
    const int jt   = blockIdx.x;     // 0..1
    const int ip   = blockIdx.y;     // 0..127
    const int b    = blockIdx.z;     // 0..1
    const int j0   = jt * TJ;
    const int i0   = ip * TI;

    // kernel base for this block: tap k piece = kb0 + k*HW (+WID for row 2)
    const float* kb0 = kern + (size_t)b * K2 * HW + (size_t)i0 * WID + j0;
    float* myring = ring + wid * (2 * STAGE_FLOATS);
    const uint32_t rb = smem_u32(myring);

    const int nc = (94 - wid) / 8 + 1;   // chunks for this warp (12 or 11)

    // issue chunk c into stage st (lane copies its own 16B per tap/row)
    auto issue = [&](int c, int st) {
        const int u    = c / 5;
        const int vb   = c % 5;
        const int vmax = (vb == 4) ? 3 : 4;
        const int k0   = u * LK + vb * 4;
        const uint32_t dst = rb + st * (STAGE_FLOATS * 4) + lane * 16;
        const float*   src = kb0 + (size_t)k0 * HW + lane * 4;
        #pragma unroll
        for (int t = 0; t < 4; t++) {
            if (t >= vmax) break;
            cp16(dst + t * 1024,       src + (size_t)t * HW);
            cp16(dst + t * 1024 + 512, src + (size_t)t * HW + WID);
        }
        cp_commit();
    };

    // start DRAM traffic immediately, before patch staging
    issue(wid, 0);
    if (nc > 1) issue(wid + 8, 1);

    // ---- stage input patch (reflect padding), all 3 channels ----
    const float* xb = x + (size_t)b * 3 * HW;
    for (int e = tid; e < PROWS * PCOLS; e += NTHR) {
        int pr = e / PCOLS;
        int pc = e - pr * PCOLS;
        int gi = i0 - PADR + pr;
        int gj = j0 - PADR + pc;
        gi = (gi < 0) ? -gi : ((gi >= HGT) ? 2 * (HGT - 1) - gi : gi);
        gj = (gj < 0) ? -gj : ((gj >= WID) ? 2 * (WID - 1) - gj : gj);
        const float* src = xb + gi * WID + gj;
        patch[(0 * PROWS + pr) * PITCH + pc] = src[0 * HW];
        patch[(1 * PROWS + pr) * PITCH + pc] = src[1 * HW];
        patch[(2 * PROWS + pr) * PITCH + pc] = src[2 * HW];
    }
    __syncthreads();

    float acc[2][3][4];
    #pragma unroll
    for (int r = 0; r < 2; r++)
        #pragma unroll
        for (int ch = 0; ch < 3; ch++)
            #pragma unroll
            for (int t = 0; t < 4; t++) acc[r][ch][t] = 0.f;

    #pragma unroll 1
    for (int s = 0; s < nc; s++) {
        const int c = wid + 8 * s;
        if (s + 1 < nc) cp_wait<1>(); else cp_wait<0>();
        __syncwarp();

        const int u    = c / 5;
        const int vb   = c % 5;
        const int vmax = (vb == 4) ? 3 : 4;
        const float4* kvp = (const float4*)(myring + (s & 1) * STAGE_FLOATS);

        // 8-float windows per channel/row (aligned float4 pair loads)
        float w[3][2][8];
        #pragma unroll
        for (int ch = 0; ch < 3; ch++) {
            #pragma unroll
            for (int r = 0; r < 2; r++) {
                const float4* prow = (const float4*)&patch[(ch * PROWS + r + u) * PITCH];
                float4 lo = prow[lane + vb], hi = prow[lane + vb + 1];
                w[ch][r][0] = lo.x; w[ch][r][1] = lo.y; w[ch][r][2] = lo.z; w[ch][r][3] = lo.w;
                w[ch][r][4] = hi.x; w[ch][r][5] = hi.y; w[ch][r][6] = hi.z; w[ch][r][7] = hi.w;
            }
        }

        #pragma unroll
        for (int t = 0; t < 4; t++) {
            if (t >= vmax) break;
            #pragma unroll
            for (int r = 0; r < 2; r++) {
                float4 kv = kvp[t * 64 + r * 32 + lane];
                #pragma unroll
                for (int ch = 0; ch < 3; ch++) {
                    acc[r][ch][0] += w[ch][r][t + 0] * kv.x;
                    acc[r][ch][1] += w[ch][r][t + 1] * kv.y;
                    acc[r][ch][2] += w[ch][r][t + 2] * kv.z;
                    acc[r][ch][3] += w[ch][r][t + 3] * kv.w;
                }
            }
        }

        if (s + 2 < nc) issue(wid + 8 * (s + 2), s & 1);
    }

    // ---- cross-warp reduction (reuse ring smem; all cp.async drained) ----
    __syncthreads();
    float4* part = (float4*)ring;    // [NW][2][3][32] float4
    #pragma unroll
    for (int r = 0; r < 2; r++)
        #pragma unroll
        for (int ch = 0; ch < 3; ch++)
            part[wid * 192 + r * 96 + ch * 32 + lane] =
                make_float4(acc[r][ch][0], acc[r][ch][1], acc[r][ch][2], acc[r][ch][3]);
    __syncthreads();

    if (tid < 192) {
        const int r  = tid / 96;
        const int ch = (tid % 96) / 32;
        const int l  = tid & 31;
        float4 sum = make_float4(0.f, 0.f, 0.f, 0.f);
        #pragma unroll
        for (int q = 0; q < NW; q++) {
            float4 p = part[q * 192 + tid];
            sum.x += p.x; sum.y += p.y; sum.z += p.z; sum.w += p.w;
        }
        const float inv = 1.0f / (float)K2;
        float* ob = out + (size_t)b * 3 * HW + (size_t)ch * HW
                        + (size_t)(i0 + r) * WID + j0 + l * 4;
        *(float4*)ob = make_float4(sum.x * inv, sum.y * inv, sum.z * inv, sum.w * inv);
    }
}

extern "C" void kernel_launch(void* const* d_in, const int* in_sizes, int n_in,
                              void* d_out, int out_size)
{
    const float* x    = (const float*)d_in[0];
    const float* kern = (const float*)d_in[1];
    // defensive: identify tensors by size (input = 393216, kernel = 47316992)
    if (n_in >= 2 && in_sizes[0] > in_sizes[1]) {
        const float* t = x; x = kern; kern = t;
    }

    cudaFuncSetAttribute(svblur_kernel,
                         cudaFuncAttributeMaxDynamicSharedMemorySize, SMEM_BYTES);

    dim3 grid(WID / TJ, HGT / TI, 2);   // (2, 128, 2) = 512 blocks, 8 warps
    svblur_kernel<<<grid, NTHR, SMEM_BYTES>>>(x, kern, (float*)d_out);
}